// round 2
// baseline (speedup 1.0000x reference)
#include <cuda_runtime.h>
#include <cstdint>

#define MAXN 100000

// ---------------- device scratch (no allocation allowed) ----------------
__device__ float d_g[(size_t)MAXN * 256];   // g[n][h][d], 102.4 MB
__device__ float d_denom[MAXN * 4];         // sum of exp(score) per (node, head)
__device__ int   g_is64;                    // edge_index dtype flag

typedef unsigned long long ull;

__device__ __forceinline__ ull pk2(float lo, float hi) {
    ull r; asm("mov.b64 %0, {%1, %2};" : "=l"(r) : "f"(lo), "f"(hi)); return r;
}
__device__ __forceinline__ float2 upk2(ull v) {
    float2 r; asm("mov.b64 {%0, %1}, %2;" : "=f"(r.x), "=f"(r.y) : "l"(v)); return r;
}
#define FMA2(acc, a, b) asm("fma.rn.f32x2 %0, %1, %2, %0;" : "+l"(acc) : "l"(a), "l"(b))

__device__ __forceinline__ void red4(float* p, float4 v) {
    asm volatile("red.global.add.v4.f32 [%0], {%1, %2, %3, %4};"
                 :: "l"(p), "f"(v.x), "f"(v.y), "f"(v.z), "f"(v.w) : "memory");
}

__device__ __forceinline__ long long load_idx(const void* p, long long i) {
    if (g_is64) return (long long)((const long long*)p)[i];
    return (long long)((const int*)p)[i];
}

// ---------------- kernel 0: detect edge_index dtype ----------------
// int64 little-endian (values < 2^31) => every odd int32 word is 0.
__global__ void detect_kernel(const int* __restrict__ p) {
    if (threadIdx.x == 0) {
        int any = 0;
        for (int i = 1; i < 256; i += 2) any |= p[i];
        g_is64 = (any == 0) ? 1 : 0;
    }
}

// ---------------- kernel 1: zero attention-out accumulator + denom ----------------
__global__ void zero_kernel(float4* __restrict__ out, int Nn) {
    int i = blockIdx.x * blockDim.x + threadIdx.x;
    int st = gridDim.x * blockDim.x;
    float4 z = make_float4(0.f, 0.f, 0.f, 0.f);
    int n4 = Nn * 16;                         // N*64 floats of `out`
    for (int j = i; j < n4; j += st) out[j] = z;
    float4* dn = (float4*)d_denom;            // N float4
    for (int j = i; j < Nn; j += st) dn[j] = z;
}

// ---------------- kernel 2: per-node g[n,h,d] = sum_c q[n,h,c] * Wk[d, h*16+c]
//                  where q = x @ Wq
__global__ void __launch_bounds__(256) prep_kernel(const float* __restrict__ x,
                                                   const float* __restrict__ Wq,
                                                   const float* __restrict__ Wk,
                                                   int Nn) {
    __shared__ float sWq[64 * 64];
    __shared__ float sWk[64 * 65];   // padded stride
    __shared__ float sq[8][64];
    int t = threadIdx.x;
    for (int i = t; i < 1024; i += 256) ((float4*)sWq)[i] = ((const float4*)Wq)[i];
    for (int i = t; i < 4096; i += 256) { int r = i >> 6, c = i & 63; sWk[r * 65 + c] = Wk[i]; }
    __syncthreads();

    int warp = t >> 5, lane = t & 31;
    int n = blockIdx.x * 8 + warp;
    if (n >= Nn) return;

    // q row: lane owns cols 2*lane, 2*lane+1
    float2 x2 = *(const float2*)&x[(size_t)n * 64 + 2 * lane];
    float qa = 0.f, qb = 0.f;
    #pragma unroll
    for (int dd = 0; dd < 32; dd++) {
        float xa = __shfl_sync(0xffffffffu, x2.x, dd);
        float xb = __shfl_sync(0xffffffffu, x2.y, dd);
        float2 w0 = *(const float2*)&sWq[(2 * dd) * 64 + 2 * lane];
        float2 w1 = *(const float2*)&sWq[(2 * dd + 1) * 64 + 2 * lane];
        qa += xa * w0.x + xb * w1.x;
        qb += xa * w0.y + xb * w1.y;
    }
    sq[warp][2 * lane]     = qa;
    sq[warp][2 * lane + 1] = qb;
    __syncwarp();

    float* gout = d_g + (size_t)n * 256;
    #pragma unroll
    for (int h = 0; h < 4; h++) {
        #pragma unroll
        for (int j = 0; j < 2; j++) {
            int d = lane + 32 * j;
            float acc = 0.f;
            #pragma unroll
            for (int c = 0; c < 16; c++)
                acc += sq[warp][16 * h + c] * sWk[d * 65 + 16 * h + c];
            gout[h * 64 + d] = acc;     // layout [n][h][d]
        }
    }
}

// ---------------- kernel 3: fused edge pass ----------------
// 64 edges / block, 256 threads.
//  1a. Z = edge_attr * x[nbr]  -> smem
//  1b. score[e,h] = (Z . g[src,h,:]) / 4 ; e = exp(score) -> smem ; red denom
//  2.  [v | edge_out] = Z @ [Wv | We]  (f32x2 FMA)
//      v path: red out[src] += e_h * v ;  We path: store edge_out + be
__global__ void __launch_bounds__(256) edge_kernel(const float* __restrict__ x,
                                                   const void*  __restrict__ eidx,
                                                   const float* __restrict__ ea,
                                                   const float* __restrict__ Wv,
                                                   const float* __restrict__ We,
                                                   const float* __restrict__ be,
                                                   float* __restrict__ outp,
                                                   float* __restrict__ eo,
                                                   long long Etot) {
    extern __shared__ __align__(16) float smem[];
    float* sW   = smem;                 // [64][128]  = Wv | We
    float* zs   = smem + 8192;          // [64][68]   Z rows (pad holds exp values)
    int*   ssrc = (int*)(smem + 8192 + 64 * 68);   // [64]
    float* sbe  = smem + 8192 + 64 * 68 + 64;      // [64]

    int t = threadIdx.x;

    // load weights: Wv -> cols [0,64), We -> cols [64,128)
    for (int i = t; i < 1024; i += 256) {
        float4 v = ((const float4*)Wv)[i];
        int r = i >> 4, c = (i & 15) * 4;
        *(float4*)&sW[r * 128 + c] = v;
    }
    for (int i = t; i < 1024; i += 256) {
        float4 v = ((const float4*)We)[i];
        int r = i >> 4, c = (i & 15) * 4;
        *(float4*)&sW[r * 128 + 64 + c] = v;
    }
    if (t < 64) sbe[t] = be[t];

    long long ebase = (long long)blockIdx.x * 64;

    // ---- phase 1a: Z ----
    int el = t >> 2, q4 = t & 3;
    long long e = ebase + el;
    bool valid = (e < Etot);
    int src = 0;
    if (valid) {
        src = (int)load_idx(eidx, e);
        long long nbr = load_idx(eidx, Etot + e);
        int d0 = q4 * 16;
        const float4* eap = (const float4*)(ea + (size_t)e * 64 + d0);
        const float4* xnp = (const float4*)(x + (size_t)nbr * 64 + d0);
        #pragma unroll
        for (int i = 0; i < 4; i++) {
            float4 a = eap[i], b = xnp[i];
            float4 z; z.x = a.x * b.x; z.y = a.y * b.y; z.z = a.z * b.z; z.w = a.w * b.w;
            *(float4*)&zs[el * 68 + d0 + 4 * i] = z;
        }
    } else {
        int d0 = q4 * 16;
        float4 z = make_float4(0.f, 0.f, 0.f, 0.f);
        #pragma unroll
        for (int i = 0; i < 4; i++) *(float4*)&zs[el * 68 + d0 + 4 * i] = z;
    }
    if (q4 == 0) ssrc[el] = src;
    __syncthreads();

    // ---- phase 1b: scores + exp ----
    {
        int h = t & 3;
        int s2 = ssrc[el];
        const float4* gp = (const float4*)(d_g + ((size_t)s2 * 4 + h) * 64);
        float sc = 0.f;
        #pragma unroll
        for (int i = 0; i < 16; i++) {
            float4 g4 = gp[i];
            float4 z4 = *(const float4*)&zs[el * 68 + 4 * i];
            sc += z4.x * g4.x + z4.y * g4.y + z4.z * g4.z + z4.w * g4.w;
        }
        float ev = valid ? __expf(sc * 0.25f) : 0.f;
        zs[el * 68 + 64 + h] = ev;
    }
    __syncthreads();

    // denom reduction (one thread per edge)
    if (t < 64 && ebase + t < Etot) {
        float4 ev4 = *(const float4*)&zs[t * 68 + 64];
        red4(&d_denom[(size_t)ssrc[t] * 4], ev4);
    }

    // ---- phase 2: GEMM [64,64] @ [64,128] ----
    int eg = t >> 4;          // 0..15 : edges eg*4..+4
    int jg = t & 15;          // 0..15 : cols  jg*8..+8
    int j0 = jg * 8;

    ull acc[4][4];
    #pragma unroll
    for (int a = 0; a < 4; a++)
        #pragma unroll
        for (int b = 0; b < 4; b++) acc[a][b] = 0ull;

    #pragma unroll 4
    for (int dd = 0; dd < 64; dd += 2) {
        ull wA[4], wB[4];
        #pragma unroll
        for (int p = 0; p < 4; p++) {
            wA[p] = *(const ull*)&sW[dd * 128 + j0 + 2 * p];
            wB[p] = *(const ull*)&sW[(dd + 1) * 128 + j0 + 2 * p];
        }
        #pragma unroll
        for (int ee = 0; ee < 4; ee++) {
            float2 z = *(const float2*)&zs[(eg * 4 + ee) * 68 + dd];
            ull zx = pk2(z.x, z.x);
            ull zy = pk2(z.y, z.y);
            #pragma unroll
            for (int p = 0; p < 4; p++) {
                FMA2(acc[ee][p], zx, wA[p]);
                FMA2(acc[ee][p], zy, wB[p]);
            }
        }
    }

    // ---- epilogue ----
    if (jg < 8) {
        // attention-out path, head = j0/16
        int h = j0 >> 4;
        #pragma unroll
        for (int ee = 0; ee < 4; ee++) {
            int eloc = eg * 4 + ee;
            if (ebase + eloc >= Etot) continue;
            float s = zs[eloc * 68 + 64 + h];
            float2 p0 = upk2(acc[ee][0]), p1 = upk2(acc[ee][1]);
            float2 p2 = upk2(acc[ee][2]), p3 = upk2(acc[ee][3]);
            float4 lo = make_float4(p0.x * s, p0.y * s, p1.x * s, p1.y * s);
            float4 hi = make_float4(p2.x * s, p2.y * s, p3.x * s, p3.y * s);
            float* dst = outp + (size_t)ssrc[eloc] * 64 + j0;
            red4(dst, lo);
            red4(dst + 4, hi);
        }
    } else {
        // edge_out path
        int jo = j0 - 64;
        float4 b0 = *(const float4*)&sbe[jo];
        float4 b1 = *(const float4*)&sbe[jo + 4];
        #pragma unroll
        for (int ee = 0; ee < 4; ee++) {
            int eloc = eg * 4 + ee;
            long long eg2 = ebase + eloc;
            if (eg2 >= Etot) continue;
            float2 p0 = upk2(acc[ee][0]), p1 = upk2(acc[ee][1]);
            float2 p2 = upk2(acc[ee][2]), p3 = upk2(acc[ee][3]);
            float4 lo = make_float4(p0.x + b0.x, p0.y + b0.y, p1.x + b0.z, p1.y + b0.w);
            float4 hi = make_float4(p2.x + b1.x, p2.y + b1.y, p3.x + b1.z, p3.y + b1.w);
            float* dst = eo + (size_t)eg2 * 64 + jo;
            *(float4*)dst = lo;
            *(float4*)(dst + 4) = hi;
        }
    }
}

// ---------------- kernel 4: normalize out by denom ----------------
__global__ void norm_kernel(float4* __restrict__ out, int Nn) {
    int i = blockIdx.x * blockDim.x + threadIdx.x;   // over N*16 float4
    if (i >= Nn * 16) return;
    int n = i >> 4;
    int h = (i >> 2) & 3;
    float dinv = 1.0f / (d_denom[n * 4 + h] + 1e-16f);
    float4 v = out[i];
    v.x *= dinv; v.y *= dinv; v.z *= dinv; v.w *= dinv;
    out[i] = v;
}

// ---------------- launch ----------------
static const int SMEM_EDGE = (8192 + 64 * 68 + 64 + 64) * 4;   // 50688 bytes

extern "C" void kernel_launch(void* const* d_in, const int* in_sizes, int n_in,
                              void* d_out, int out_size) {
    const float* x   = (const float*)d_in[0];
    const void*  eix = d_in[1];
    const float* ea  = (const float*)d_in[2];
    const float* Wq  = (const float*)d_in[3];
    const float* Wk  = (const float*)d_in[4];
    const float* Wv  = (const float*)d_in[5];
    const float* We  = (const float*)d_in[6];
    const float* be  = (const float*)d_in[7];

    int       Nn   = in_sizes[0] / 64;        // from x [N,64]
    long long Etot = (long long)in_sizes[2] / 64;   // from edge_attr [E,64]

    float* outp = (float*)d_out;
    float* eo   = outp + (size_t)Nn * 64;

    cudaFuncSetAttribute(edge_kernel, cudaFuncAttributeMaxDynamicSharedMemorySize, SMEM_EDGE);

    detect_kernel<<<1, 32>>>((const int*)eix);
    zero_kernel<<<2048, 256>>>((float4*)outp, Nn);
    prep_kernel<<<(Nn + 7) / 8, 256>>>(x, Wq, Wk, Nn);
    int eblocks = (int)((Etot + 63) / 64);
    edge_kernel<<<eblocks, 256, SMEM_EDGE>>>(x, eix, ea, Wv, We, be, outp, eo, Etot);
    norm_kernel<<<(Nn * 16 + 255) / 256, 256>>>((float4*)outp, Nn);
}

// round 4
// speedup vs baseline: 1.3909x; 1.3909x over previous
#include <cuda_runtime.h>
#include <cuda_fp16.h>
#include <cstdint>

#define MAXN 100000

// ---------------- device scratch ----------------
__device__ float d_q[(size_t)MAXN * 64];                 // q[n][h*16+c], 25.6 MB
__device__ float d_denom[MAXN * 4];                      // per (node, head)
__device__ __align__(16) __half d_Bimg[2 * 192 * 72];    // B image: [hi|lo][col][k-pad72]
__device__ int g_is64;

// ---------------- helpers ----------------
__device__ __forceinline__ void red4(float* p, float4 v) {
    asm volatile("red.global.add.v4.f32 [%0], {%1, %2, %3, %4};"
                 :: "l"(p), "f"(v.x), "f"(v.y), "f"(v.z), "f"(v.w) : "memory");
}
__device__ __forceinline__ void red2(float* p, float a, float b) {
    asm volatile("red.global.add.v2.f32 [%0], {%1, %2};"
                 :: "l"(p), "f"(a), "f"(b) : "memory");
}
__device__ __forceinline__ long long load_idx(const void* p, long long i) {
    if (g_is64) return ((const long long*)p)[i];
    return (long long)((const int*)p)[i];
}
__device__ __forceinline__ uint32_t pack_h2(float a, float b) {
    __half2 h = __floats2half2_rn(a, b);   // a -> low
    return *(uint32_t*)&h;
}
__device__ __forceinline__ void mma16816(float c[4], const uint32_t a[4],
                                         uint32_t b0, uint32_t b1) {
    asm volatile("mma.sync.aligned.m16n8k16.row.col.f32.f16.f16.f32 "
                 "{%0,%1,%2,%3}, {%4,%5,%6,%7}, {%8,%9}, {%0,%1,%2,%3};"
                 : "+f"(c[0]), "+f"(c[1]), "+f"(c[2]), "+f"(c[3])
                 : "r"(a[0]), "r"(a[1]), "r"(a[2]), "r"(a[3]), "r"(b0), "r"(b1));
}

// ---------------- smem layout (bytes), 512 threads, 256 edges/CTA ----------------
#define SM_SRC  0                         // int[256]           (1024)
#define SM_ATT  1024                      // float[256*4]       (4096)
#define SM_BE   5120                      // float[64]          (256)
#define SM_BHI  5376                      // half[192][72]      (27648)
#define SM_BLO  33024                     // half[192][72]      (27648)
#define SM_AHI  60672                     // half[256][72]      (36864)
#define SM_ALO  97536                     // half[256][72]      (36864)
#define SM_K    134400                    // float[256][72]     (73728)
#define SMEM_BYTES 208128

// ================= kernel 0: dtype detect =================
__global__ void detect_kernel(const int* __restrict__ p) {
    if (threadIdx.x == 0) {
        int any = 0;
        for (int i = 1; i < 256; i += 2) any |= p[i];
        g_is64 = (any == 0) ? 1 : 0;
    }
}

// ================= kernel 1: zero out + denom =================
__global__ void zero_kernel(float4* __restrict__ out, int Nn) {
    int i = blockIdx.x * blockDim.x + threadIdx.x;
    int st = gridDim.x * blockDim.x;
    float4 z = make_float4(0.f, 0.f, 0.f, 0.f);
    int n4 = Nn * 16;
    for (int j = i; j < n4; j += st) out[j] = z;
    float4* dn = (float4*)d_denom;
    for (int j = i; j < Nn; j += st) dn[j] = z;
}

// ================= kernel 2: q = x @ Wq =================
__global__ void __launch_bounds__(256) prep_kernel(const float* __restrict__ x,
                                                   const float* __restrict__ Wq,
                                                   int Nn) {
    __shared__ float sWq[64 * 64];
    int t = threadIdx.x;
    for (int i = t; i < 1024; i += 256) ((float4*)sWq)[i] = ((const float4*)Wq)[i];
    __syncthreads();

    int warp = t >> 5, lane = t & 31;
    int n = blockIdx.x * 8 + warp;
    if (n >= Nn) return;

    float2 x2 = *(const float2*)&x[(size_t)n * 64 + 2 * lane];
    float qa = 0.f, qb = 0.f;
    #pragma unroll
    for (int dd = 0; dd < 32; dd++) {
        float xa = __shfl_sync(0xffffffffu, x2.x, dd);
        float xb = __shfl_sync(0xffffffffu, x2.y, dd);
        float2 w0 = *(const float2*)&sWq[(2 * dd) * 64 + 2 * lane];
        float2 w1 = *(const float2*)&sWq[(2 * dd + 1) * 64 + 2 * lane];
        qa += xa * w0.x + xb * w1.x;
        qb += xa * w0.y + xb * w1.y;
    }
    d_q[(size_t)n * 64 + 2 * lane]     = qa;
    d_q[(size_t)n * 64 + 2 * lane + 1] = qb;
}

// ================= kernel 3: build B image =================
// cols: 0..63 Wv, 64..127 We, 128..191 Wk.  B[col][k] = W[k][col], fp16 hi/lo split.
__global__ void build_b(const float* __restrict__ Wv, const float* __restrict__ We,
                        const float* __restrict__ Wk) {
    int n = threadIdx.x;
    if (n >= 192) return;
    const float* W = (n < 64) ? Wv : ((n < 128) ? We : Wk);
    int nn = n & 63;
    for (int k = 0; k < 64; k++) {
        float w = W[k * 64 + nn];
        __half h = __float2half_rn(w);
        __half l = __float2half_rn(w - __half2float(h));
        d_Bimg[n * 72 + k]            = h;
        d_Bimg[192 * 72 + n * 72 + k] = l;
    }
}

// ================= kernel 4: fused edge pass (mma.sync) =================
__global__ void __launch_bounds__(512, 1) edge_kernel(const float* __restrict__ x,
                                                      const void*  __restrict__ eidx,
                                                      const float* __restrict__ ea,
                                                      const float* __restrict__ be,
                                                      float* __restrict__ outp,
                                                      float* __restrict__ eo,
                                                      long long Etot) {
    extern __shared__ __align__(16) char smem[];
    int*   ssrc = (int*)(smem + SM_SRC);
    float* satt = (float*)(smem + SM_ATT);
    float* sbe  = (float*)(smem + SM_BE);

    int t = threadIdx.x, wid = t >> 5, lane = t & 31;
    int g = lane >> 2, t4 = lane & 3;

    long long ebase = (long long)blockIdx.x * 256;

    // ---- copy B image (55296 B) ----
    {
        const uint4* bs = (const uint4*)d_Bimg;
        uint4* bd = (uint4*)(smem + SM_BHI);
        #pragma unroll
        for (int i = 0; i < 7; i++) {
            int idx = t + 512 * i;
            if (idx < 3456) bd[idx] = bs[idx];
        }
    }
    if (t < 64) sbe[t] = be[t];

    // ---- Z = ea * x[nbr], fp16-split into A tiles ----
    {
        int el = t >> 1, half = t & 1;
        long long e = ebase + el;
        bool valid = (e < Etot);
        int src = 0; long long nbr = 0;
        if (valid) { src = (int)load_idx(eidx, e); nbr = load_idx(eidx, Etot + e); }
        if (half == 0) ssrc[el] = src;
        const float4* eap = (const float4*)(ea + (size_t)e * 64 + half * 32);
        const float4* xnp = (const float4*)(x + (size_t)nbr * 64 + half * 32);
        char* ah = smem + SM_AHI + el * 144 + half * 64;
        char* al = smem + SM_ALO + el * 144 + half * 64;
        #pragma unroll
        for (int i = 0; i < 4; i++) {
            float z[8];
            if (valid) {
                float4 a0 = eap[2 * i], b0 = xnp[2 * i];
                float4 a1 = eap[2 * i + 1], b1 = xnp[2 * i + 1];
                z[0] = a0.x * b0.x; z[1] = a0.y * b0.y; z[2] = a0.z * b0.z; z[3] = a0.w * b0.w;
                z[4] = a1.x * b1.x; z[5] = a1.y * b1.y; z[6] = a1.z * b1.z; z[7] = a1.w * b1.w;
            } else {
                #pragma unroll
                for (int j = 0; j < 8; j++) z[j] = 0.f;
            }
            uint4 hv, lv;
            float h0, h1;
            h0 = __half2float(__float2half_rn(z[0])); h1 = __half2float(__float2half_rn(z[1]));
            hv.x = pack_h2(z[0], z[1]); lv.x = pack_h2(z[0] - h0, z[1] - h1);
            h0 = __half2float(__float2half_rn(z[2])); h1 = __half2float(__float2half_rn(z[3]));
            hv.y = pack_h2(z[2], z[3]); lv.y = pack_h2(z[2] - h0, z[3] - h1);
            h0 = __half2float(__float2half_rn(z[4])); h1 = __half2float(__float2half_rn(z[5]));
            hv.z = pack_h2(z[4], z[5]); lv.z = pack_h2(z[4] - h0, z[5] - h1);
            h0 = __half2float(__float2half_rn(z[6])); h1 = __half2float(__float2half_rn(z[7]));
            hv.w = pack_h2(z[6], z[7]); lv.w = pack_h2(z[6] - h0, z[7] - h1);
            *(uint4*)(ah + 16 * i) = hv;
            *(uint4*)(al + 16 * i) = lv;
        }
    }
    __syncthreads();

    // ---- A fragments: 4 k-steps x 4 regs, hi + lo ----
    uint32_t afh[16], afl[16];
    {
        int row0 = wid * 16 + g;
        const char* Ah = smem + SM_AHI;
        const char* Al = smem + SM_ALO;
        #pragma unroll
        for (int ks = 0; ks < 4; ks++) {
            int base = row0 * 144 + ks * 32 + t4 * 4;
            afh[ks * 4 + 0] = *(const uint32_t*)(Ah + base);
            afh[ks * 4 + 1] = *(const uint32_t*)(Ah + base + 8 * 144);
            afh[ks * 4 + 2] = *(const uint32_t*)(Ah + base + 16);
            afh[ks * 4 + 3] = *(const uint32_t*)(Ah + base + 8 * 144 + 16);
            afl[ks * 4 + 0] = *(const uint32_t*)(Al + base);
            afl[ks * 4 + 1] = *(const uint32_t*)(Al + base + 8 * 144);
            afl[ks * 4 + 2] = *(const uint32_t*)(Al + base + 16);
            afl[ks * 4 + 3] = *(const uint32_t*)(Al + base + 8 * 144 + 16);
        }
    }

    const char* Bh = smem + SM_BHI;
    const char* Bl = smem + SM_BLO;
    float* kb = (float*)(smem + SM_K);

    // ---- stage 1: k = Z @ Wk  (B cols 128..191) -> kbuf ----
    #pragma unroll
    for (int j = 0; j < 8; j++) {
        int nc = 128 + j * 8;
        float c[4] = {0.f, 0.f, 0.f, 0.f};
        #pragma unroll
        for (int ks = 0; ks < 4; ks++) {
            int boff = (nc + g) * 144 + ks * 32 + t4 * 4;
            uint32_t bh0 = *(const uint32_t*)(Bh + boff);
            uint32_t bh1 = *(const uint32_t*)(Bh + boff + 16);
            uint32_t bl0 = *(const uint32_t*)(Bl + boff);
            uint32_t bl1 = *(const uint32_t*)(Bl + boff + 16);
            mma16816(c, &afh[ks * 4], bh0, bh1);
            mma16816(c, &afh[ks * 4], bl0, bl1);
            mma16816(c, &afl[ks * 4], bh0, bh1);
        }
        int row0 = wid * 16 + g;
        int kc = j * 8 + 2 * t4;
        *(float2*)&kb[row0 * 72 + kc]       = make_float2(c[0], c[1]);
        *(float2*)&kb[(row0 + 8) * 72 + kc] = make_float2(c[2], c[3]);
    }
    __syncthreads();

    // ---- score pass: att = exp(q[src] . k / 4) ----
    {
        int el = t >> 1, hh = (t & 1) * 2;
        bool valid = (ebase + el) < Etot;
        int src = ssrc[el];
        const float4* qp = (const float4*)(d_q + (size_t)src * 64 + hh * 16);
        const float* kr = kb + el * 72 + hh * 16;
        float s0 = 0.f, s1 = 0.f;
        #pragma unroll
        for (int i = 0; i < 4; i++) {
            float4 q4 = qp[i];
            float4 k4 = *(const float4*)(kr + 4 * i);
            s0 += q4.x * k4.x + q4.y * k4.y + q4.z * k4.z + q4.w * k4.w;
        }
        #pragma unroll
        for (int i = 0; i < 4; i++) {
            float4 q4 = qp[4 + i];
            float4 k4 = *(const float4*)(kr + 16 + 4 * i);
            s1 += q4.x * k4.x + q4.y * k4.y + q4.z * k4.z + q4.w * k4.w;
        }
        satt[el * 4 + hh]     = valid ? __expf(s0 * 0.25f) : 0.f;
        satt[el * 4 + hh + 1] = valid ? __expf(s1 * 0.25f) : 0.f;
    }
    __syncthreads();

    // denom scatter
    if (t < 256 && (ebase + t) < Etot)
        red4(&d_denom[(size_t)ssrc[t] * 4], *(float4*)&satt[t * 4]);

    // ---- stage 2: [v | eo] = Z @ [Wv | We], epilogue per n-tile ----
    int row0 = wid * 16 + g;
    bool v0 = (ebase + row0) < Etot;
    bool v1 = (ebase + row0 + 8) < Etot;
    int src0 = ssrc[row0], src1 = ssrc[row0 + 8];

    #pragma unroll
    for (int nt = 0; nt < 16; nt++) {
        int nc = nt * 8;
        float c[4] = {0.f, 0.f, 0.f, 0.f};
        #pragma unroll
        for (int ks = 0; ks < 4; ks++) {
            int boff = (nc + g) * 144 + ks * 32 + t4 * 4;
            uint32_t bh0 = *(const uint32_t*)(Bh + boff);
            uint32_t bh1 = *(const uint32_t*)(Bh + boff + 16);
            uint32_t bl0 = *(const uint32_t*)(Bl + boff);
            uint32_t bl1 = *(const uint32_t*)(Bl + boff + 16);
            mma16816(c, &afh[ks * 4], bh0, bh1);
            mma16816(c, &afh[ks * 4], bl0, bl1);
            mma16816(c, &afl[ks * 4], bh0, bh1);
        }
        int col = nc + 2 * t4;
        if (nt < 8) {
            // v path: weight by att, scatter-add to out[src]
            int head = col >> 4;
            float a0 = satt[row0 * 4 + head];
            float a1 = satt[(row0 + 8) * 4 + head];
            if (v0) red2(outp + (size_t)src0 * 64 + col, c[0] * a0, c[1] * a0);
            if (v1) red2(outp + (size_t)src1 * 64 + col, c[2] * a1, c[3] * a1);
        } else {
            // eo path: add bias, store
            int ec = col - 64;
            float b0 = sbe[ec], b1 = sbe[ec + 1];
            if (v0) *(float2*)(eo + (ebase + row0) * 64 + ec)       = make_float2(c[0] + b0, c[1] + b1);
            if (v1) *(float2*)(eo + (ebase + row0 + 8) * 64 + ec)   = make_float2(c[2] + b0, c[3] + b1);
        }
    }
}

// ================= kernel 5: normalize =================
__global__ void norm_kernel(float4* __restrict__ out, int Nn) {
    int i = blockIdx.x * blockDim.x + threadIdx.x;
    if (i >= Nn * 16) return;
    int n = i >> 4;
    int h = (i >> 2) & 3;
    float dinv = 1.0f / (d_denom[n * 4 + h] + 1e-16f);
    float4 v = out[i];
    v.x *= dinv; v.y *= dinv; v.z *= dinv; v.w *= dinv;
    out[i] = v;
}

// ================= launch =================
extern "C" void kernel_launch(void* const* d_in, const int* in_sizes, int n_in,
                              void* d_out, int out_size) {
    const float* x   = (const float*)d_in[0];
    const void*  eix = d_in[1];
    const float* ea  = (const float*)d_in[2];
    const float* Wq  = (const float*)d_in[3];
    const float* Wk  = (const float*)d_in[4];
    const float* Wv  = (const float*)d_in[5];
    const float* We  = (const float*)d_in[6];
    const float* be  = (const float*)d_in[7];

    int       Nn   = in_sizes[0] / 64;
    long long Etot = (long long)in_sizes[2] / 64;

    float* outp = (float*)d_out;
    float* eo   = outp + (size_t)Nn * 64;

    static int cfg = 0;
    if (!cfg) {
        cudaFuncSetAttribute(edge_kernel, cudaFuncAttributeMaxDynamicSharedMemorySize, SMEM_BYTES);
        cfg = 1;
    }

    detect_kernel<<<1, 32>>>((const int*)eix);
    zero_kernel<<<2048, 256>>>((float4*)outp, Nn);
    prep_kernel<<<(Nn + 7) / 8, 256>>>(x, Wq, Nn);
    build_b<<<1, 192>>>(Wv, We, Wk);
    int eblocks = (int)((Etot + 255) / 256);
    edge_kernel<<<eblocks, 512, SMEM_BYTES>>>(x, eix, ea, be, outp, eo, Etot);
    norm_kernel<<<(Nn * 16 + 255) / 256, 256>>>((float4*)outp, Nn);
}

// round 5
// speedup vs baseline: 2.0395x; 1.4664x over previous
#include <cuda_runtime.h>
#include <cuda_fp16.h>
#include <cstdint>

#define MAXN 100000
#define EPB  384            // edges per block
#define NTHR 384

// ---------------- device scratch ----------------
__device__ float d_q[(size_t)MAXN * 64];                 // q[n][h*16+c], 25.6 MB
__device__ float d_denom[MAXN * 4];                      // per (node, head)
__device__ __align__(16) __half d_Bimg[2 * 192 * 72];    // [hi|lo][col][k pad 72]
__device__ int g_is64;

// ---------------- helpers ----------------
__device__ __forceinline__ void red4(float* p, float4 v) {
    asm volatile("red.global.add.v4.f32 [%0], {%1, %2, %3, %4};"
                 :: "l"(p), "f"(v.x), "f"(v.y), "f"(v.z), "f"(v.w) : "memory");
}
__device__ __forceinline__ long long load_idx(const void* p, long long i) {
    if (g_is64) return ((const long long*)p)[i];
    return (long long)((const int*)p)[i];
}
__device__ __forceinline__ uint32_t smem_u32(const void* p) {
    uint32_t a;
    asm("{ .reg .u64 t; cvta.to.shared.u64 t, %1; cvt.u32.u64 %0, t; }" : "=r"(a) : "l"(p));
    return a;
}
__device__ __forceinline__ uint32_t pack_h2(float a, float b) {
    __half2 h = __floats2half2_rn(a, b);
    return *(uint32_t*)&h;
}
__device__ __forceinline__ void mma16816(float c[4], const uint32_t a[4],
                                         uint32_t b0, uint32_t b1) {
    asm volatile("mma.sync.aligned.m16n8k16.row.col.f32.f16.f16.f32 "
                 "{%0,%1,%2,%3}, {%4,%5,%6,%7}, {%8,%9}, {%0,%1,%2,%3};"
                 : "+f"(c[0]), "+f"(c[1]), "+f"(c[2]), "+f"(c[3])
                 : "r"(a[0]), "r"(a[1]), "r"(a[2]), "r"(a[3]), "r"(b0), "r"(b1));
}
#define LDMX4(r, a)                                                        \
    asm volatile("ldmatrix.sync.aligned.m8n8.x4.shared.b16 {%0,%1,%2,%3}, [%4];" \
        : "=r"((r)[0]), "=r"((r)[1]), "=r"((r)[2]), "=r"((r)[3]) : "r"(a))
#define LDMX2(r, a)                                                        \
    asm volatile("ldmatrix.sync.aligned.m8n8.x2.shared.b16 {%0,%1}, [%2];" \
        : "=r"((r)[0]), "=r"((r)[1]) : "r"(a))

// ---------------- smem layout (bytes) ----------------
#define SM_SRC 0                       // int[384]            1536
#define SM_BE  1536                    // float[64]           256
#define SM_BHI 1792                    // half[192][72]       27648
#define SM_BLO 29440                   // half[192][72]       27648
#define SM_AHI 57088                   // half[384][72]       55296
#define SM_ALO 112384                  // half[384][72]       55296
#define SMEM_BYTES 167680

// ================= kernel 0: dtype detect =================
__global__ void detect_kernel(const int* __restrict__ p) {
    if (threadIdx.x == 0) {
        int any = 0;
        for (int i = 1; i < 256; i += 2) any |= p[i];
        g_is64 = (any == 0) ? 1 : 0;
    }
}

// ================= kernel 1: zero out + denom =================
__global__ void zero_kernel(float4* __restrict__ out, int Nn) {
    int i = blockIdx.x * blockDim.x + threadIdx.x;
    int st = gridDim.x * blockDim.x;
    float4 z = make_float4(0.f, 0.f, 0.f, 0.f);
    int n4 = Nn * 16;
    for (int j = i; j < n4; j += st) out[j] = z;
    float4* dn = (float4*)d_denom;
    for (int j = i; j < Nn; j += st) dn[j] = z;
}

// ================= kernel 2: q = x @ Wq  (+ block 0 builds B image) =================
__global__ void __launch_bounds__(256) prep_kernel(const float* __restrict__ x,
                                                   const float* __restrict__ Wq,
                                                   const float* __restrict__ Wv,
                                                   const float* __restrict__ We,
                                                   const float* __restrict__ Wk,
                                                   int Nn) {
    // block 0: build fp16 hi/lo split B image. cols: 0..63 Wv, 64..127 We, 128..191 Wk
    if (blockIdx.x == 0 && threadIdx.x < 192) {
        int n = threadIdx.x;
        const float* W = (n < 64) ? Wv : ((n < 128) ? We : Wk);
        int nn = n & 63;
        for (int k = 0; k < 64; k++) {
            float w = W[k * 64 + nn];
            __half h = __float2half_rn(w);
            __half l = __float2half_rn(w - __half2float(h));
            d_Bimg[n * 72 + k]            = h;
            d_Bimg[192 * 72 + n * 72 + k] = l;
        }
    }

    __shared__ float sWq[64 * 64];
    int t = threadIdx.x;
    for (int i = t; i < 1024; i += 256) ((float4*)sWq)[i] = ((const float4*)Wq)[i];
    __syncthreads();

    int warp = t >> 5, lane = t & 31;
    int n = blockIdx.x * 8 + warp;
    if (n >= Nn) return;

    float2 x2 = *(const float2*)&x[(size_t)n * 64 + 2 * lane];
    float qa = 0.f, qb = 0.f;
    #pragma unroll
    for (int dd = 0; dd < 32; dd++) {
        float xa = __shfl_sync(0xffffffffu, x2.x, dd);
        float xb = __shfl_sync(0xffffffffu, x2.y, dd);
        float2 w0 = *(const float2*)&sWq[(2 * dd) * 64 + 2 * lane];
        float2 w1 = *(const float2*)&sWq[(2 * dd + 1) * 64 + 2 * lane];
        qa += xa * w0.x + xb * w1.x;
        qb += xa * w0.y + xb * w1.y;
    }
    d_q[(size_t)n * 64 + 2 * lane]     = qa;
    d_q[(size_t)n * 64 + 2 * lane + 1] = qb;
}

// ================= kernel 3: fused edge pass =================
__global__ void __launch_bounds__(NTHR, 1) edge_kernel(const float* __restrict__ x,
                                                       const void*  __restrict__ eidx,
                                                       const float* __restrict__ ea,
                                                       const float* __restrict__ be,
                                                       float* __restrict__ outp,
                                                       float* __restrict__ eo,
                                                       long long Etot) {
    extern __shared__ __align__(16) char smem[];
    uint32_t smb = smem_u32(smem);
    int t = threadIdx.x, w = t >> 5, l = t & 31;
    int g = l >> 2, t4 = l & 3;

    int*   ssrc = (int*)(smem + SM_SRC);
    float* sbe  = (float*)(smem + SM_BE);

    long long ebase = (long long)blockIdx.x * EPB;

    // ---- B copy (55296 B, contiguous hi|lo) ----
    {
        const uint4* bs = (const uint4*)d_Bimg;
        uint4* bd = (uint4*)(smem + SM_BHI);
        #pragma unroll
        for (int i = 0; i < 9; i++) bd[t + NTHR * i] = bs[t + NTHR * i];
    }
    if (t < 64) sbe[t] = be[t];

    // ---- A build: edge = ebase + t, Z = ea * x[nbr], fp16 hi/lo split ----
    {
        long long e = ebase + t;
        bool valid = (e < Etot);
        int src = 0; long long nbr = 0;
        if (valid) { src = (int)load_idx(eidx, e); nbr = load_idx(eidx, Etot + e); }
        ssrc[t] = src;
        const float4* eap = (const float4*)(ea + (size_t)e * 64);
        const float4* xnp = (const float4*)(x + (size_t)nbr * 64);
        char* ah = smem + SM_AHI + t * 144;
        char* al = smem + SM_ALO + t * 144;
        #pragma unroll
        for (int i = 0; i < 8; i++) {
            float z[8];
            if (valid) {
                float4 a0 = eap[2 * i], b0 = xnp[2 * i];
                float4 a1 = eap[2 * i + 1], b1 = xnp[2 * i + 1];
                z[0] = a0.x * b0.x; z[1] = a0.y * b0.y; z[2] = a0.z * b0.z; z[3] = a0.w * b0.w;
                z[4] = a1.x * b1.x; z[5] = a1.y * b1.y; z[6] = a1.z * b1.z; z[7] = a1.w * b1.w;
            } else {
                #pragma unroll
                for (int j = 0; j < 8; j++) z[j] = 0.f;
            }
            uint4 hv, lv;
            float h0, h1;
            h0 = __half2float(__float2half_rn(z[0])); h1 = __half2float(__float2half_rn(z[1]));
            hv.x = pack_h2(z[0], z[1]); lv.x = pack_h2(z[0] - h0, z[1] - h1);
            h0 = __half2float(__float2half_rn(z[2])); h1 = __half2float(__float2half_rn(z[3]));
            hv.y = pack_h2(z[2], z[3]); lv.y = pack_h2(z[2] - h0, z[3] - h1);
            h0 = __half2float(__float2half_rn(z[4])); h1 = __half2float(__float2half_rn(z[5]));
            hv.z = pack_h2(z[4], z[5]); lv.z = pack_h2(z[4] - h0, z[5] - h1);
            h0 = __half2float(__float2half_rn(z[6])); h1 = __half2float(__float2half_rn(z[7]));
            hv.w = pack_h2(z[6], z[7]); lv.w = pack_h2(z[6] - h0, z[7] - h1);
            *(uint4*)(ah + 16 * i) = hv;
            *(uint4*)(al + 16 * i) = lv;
        }
    }
    __syncthreads();

    // ---------------- per-warp: rows rb .. rb+31 (2 m-tiles) ----------------
    int rb = w * 32;

    // src values and validity for this lane's 4 rows
    int  srow[2][2];
    bool vrow[2][2];
    #pragma unroll
    for (int mt = 0; mt < 2; mt++)
        #pragma unroll
        for (int r = 0; r < 2; r++) {
            int row = rb + mt * 16 + g + 8 * r;
            srow[mt][r] = ssrc[row];
            vrow[mt][r] = (ebase + row) < Etot;
        }

    // ---- A fragments via ldmatrix.x4 ----
    uint32_t afh[2][4][4], afl[2][4][4];
    {
        uint32_t rowsel = (uint32_t)(l & 15);
        uint32_t koff = (uint32_t)(l >> 4) * 16;
        #pragma unroll
        for (int mt = 0; mt < 2; mt++) {
            uint32_t ab = smb + SM_AHI + (rb + mt * 16 + rowsel) * 144 + koff;
            #pragma unroll
            for (int ks = 0; ks < 4; ks++) {
                LDMX4(afh[mt][ks], ab + ks * 32);
                LDMX4(afl[mt][ks], ab + (SM_ALO - SM_AHI) + ks * 32);
            }
        }
    }

    // B per-lane base (lanes 0-15 meaningful for x2)
    uint32_t bb = smb + SM_BHI + (uint32_t)(l & 7) * 144 + (uint32_t)((l >> 3) & 1) * 16;

    // ---- k path (B cols 128..191) + in-register scores ----
    float ps[2][2][4];
    #pragma unroll
    for (int mt = 0; mt < 2; mt++)
        #pragma unroll
        for (int r = 0; r < 2; r++)
            #pragma unroll
            for (int h = 0; h < 4; h++) ps[mt][r][h] = 0.f;

    #pragma unroll
    for (int mt = 0; mt < 2; mt++) {
        const float* q0 = d_q + (size_t)srow[mt][0] * 64;
        const float* q1 = d_q + (size_t)srow[mt][1] * 64;
        #pragma unroll
        for (int j = 0; j < 8; j++) {
            float c[4] = {0.f, 0.f, 0.f, 0.f};
            #pragma unroll
            for (int ks = 0; ks < 4; ks++) {
                uint32_t bo = (uint32_t)(128 + 8 * j) * 144 + ks * 32;
                uint32_t bh[2], bl[2];
                LDMX2(bh, bb + bo);
                LDMX2(bl, bb + bo + 27648);
                mma16816(c, afh[mt][ks], bh[0], bh[1]);
                mma16816(c, afh[mt][ks], bl[0], bl[1]);
                mma16816(c, afl[mt][ks], bh[0], bh[1]);
            }
            int jc = 8 * j + 2 * t4;
            float2 qa = *(const float2*)(q0 + jc);
            float2 qb = *(const float2*)(q1 + jc);
            ps[mt][0][j >> 1] += c[0] * qa.x + c[1] * qa.y;
            ps[mt][1][j >> 1] += c[2] * qb.x + c[3] * qb.y;
        }
    }

    // quad-reduce + exp -> att (all lanes hold all 16)
    float att[2][2][4];
    #pragma unroll
    for (int mt = 0; mt < 2; mt++)
        #pragma unroll
        for (int r = 0; r < 2; r++)
            #pragma unroll
            for (int h = 0; h < 4; h++) {
                float v = ps[mt][r][h];
                v += __shfl_xor_sync(0xffffffffu, v, 1);
                v += __shfl_xor_sync(0xffffffffu, v, 2);
                att[mt][r][h] = __expf(v * 0.25f);
            }

    // denom scatter: lane t4 = mt*2+r handles one row
    #pragma unroll
    for (int mt = 0; mt < 2; mt++)
        #pragma unroll
        for (int r = 0; r < 2; r++)
            if (t4 == mt * 2 + r && vrow[mt][r])
                red4(&d_denom[(size_t)srow[mt][r] * 4],
                     make_float4(att[mt][r][0], att[mt][r][1], att[mt][r][2], att[mt][r][3]));

    // ---- v | eo sweep (B cols 0..127) ----
    bool even = ((t4 & 1) == 0);
    int colb = even ? (2 * t4) : (2 * (t4 - 1));   // 0 or 4

    #pragma unroll
    for (int mt = 0; mt < 2; mt++) {
        int rg = rb + mt * 16 + g;
        #pragma unroll
        for (int j = 0; j < 16; j++) {
            float c[4] = {0.f, 0.f, 0.f, 0.f};
            #pragma unroll
            for (int ks = 0; ks < 4; ks++) {
                uint32_t bo = (uint32_t)(8 * j) * 144 + ks * 32;
                uint32_t bh[2], bl[2];
                LDMX2(bh, bb + bo);
                LDMX2(bl, bb + bo + 27648);
                mma16816(c, afh[mt][ks], bh[0], bh[1]);
                mma16816(c, afh[mt][ks], bl[0], bl[1]);
                mma16816(c, afl[mt][ks], bh[0], bh[1]);
            }
            if (j < 8) {
                int h = j >> 1;
                c[0] *= att[mt][0][h]; c[1] *= att[mt][0][h];
                c[2] *= att[mt][1][h]; c[3] *= att[mt][1][h];
            } else {
                int ec = 8 * (j - 8) + 2 * t4;
                float b0 = sbe[ec], b1 = sbe[ec + 1];
                c[0] += b0; c[1] += b1; c[2] += b0; c[3] += b1;
            }
            float o0 = __shfl_xor_sync(0xffffffffu, c[0], 1);
            float o1 = __shfl_xor_sync(0xffffffffu, c[1], 1);
            float o2 = __shfl_xor_sync(0xffffffffu, c[2], 1);
            float o3 = __shfl_xor_sync(0xffffffffu, c[3], 1);
            float4 vv = even ? make_float4(c[0], c[1], o0, o1)
                             : make_float4(o2, o3, c[2], c[3]);
            int r = even ? 0 : 1;
            if (vrow[mt][r]) {
                if (j < 8) {
                    red4(outp + (size_t)srow[mt][r] * 64 + 8 * j + colb, vv);
                } else {
                    long long row = ebase + rg + 8 * r;
                    *(float4*)(eo + row * 64 + 8 * (j - 8) + colb) = vv;
                }
            }
        }
    }
}

// ================= kernel 4: normalize =================
__global__ void norm_kernel(float4* __restrict__ out, int Nn) {
    int i = blockIdx.x * blockDim.x + threadIdx.x;
    if (i >= Nn * 16) return;
    int n = i >> 4;
    int h = (i >> 2) & 3;
    float dinv = 1.0f / (d_denom[n * 4 + h] + 1e-16f);
    float4 v = out[i];
    v.x *= dinv; v.y *= dinv; v.z *= dinv; v.w *= dinv;
    out[i] = v;
}

// ================= launch =================
extern "C" void kernel_launch(void* const* d_in, const int* in_sizes, int n_in,
                              void* d_out, int out_size) {
    const float* x   = (const float*)d_in[0];
    const void*  eix = d_in[1];
    const float* ea  = (const float*)d_in[2];
    const float* Wq  = (const float*)d_in[3];
    const float* Wk  = (const float*)d_in[4];
    const float* Wv  = (const float*)d_in[5];
    const float* We  = (const float*)d_in[6];
    const float* be  = (const float*)d_in[7];

    int       Nn   = in_sizes[0] / 64;
    long long Etot = (long long)in_sizes[2] / 64;

    float* outp = (float*)d_out;
    float* eo   = outp + (size_t)Nn * 64;

    static int cfg = 0;
    if (!cfg) {
        cudaFuncSetAttribute(edge_kernel, cudaFuncAttributeMaxDynamicSharedMemorySize, SMEM_BYTES);
        cfg = 1;
    }

    detect_kernel<<<1, 32>>>((const int*)eix);
    zero_kernel<<<2048, 256>>>((float4*)outp, Nn);
    prep_kernel<<<(Nn + 7) / 8, 256>>>(x, Wq, Wv, We, Wk, Nn);
    int eblocks = (int)((Etot + EPB - 1) / EPB);
    edge_kernel<<<eblocks, NTHR, SMEM_BYTES>>>(x, eix, ea, be, outp, eo, Etot);
    norm_kernel<<<(Nn * 16 + 255) / 256, 256>>>((float4*)outp, Nn);
}

// round 6
// speedup vs baseline: 2.2301x; 1.0934x over previous
#include <cuda_runtime.h>
#include <cuda_fp16.h>
#include <cstdint>

#define MAXN 100000
#define EPB  384            // edges per block
#define NTHR 384

// ---------------- device scratch ----------------
__device__ float d_q[(size_t)MAXN * 64];                 // q[n][h*16+c], 25.6 MB
__device__ float d_denom[MAXN * 4];                      // per (node, head)
__device__ __align__(16) __half d_Bimg[2 * 192 * 72];    // [hi|lo][col][k pad 72]
__device__ int g_is64;

// ---------------- helpers ----------------
__device__ __forceinline__ void red4(float* p, float4 v) {
    asm volatile("red.global.add.v4.f32 [%0], {%1, %2, %3, %4};"
                 :: "l"(p), "f"(v.x), "f"(v.y), "f"(v.z), "f"(v.w) : "memory");
}
__device__ __forceinline__ long long load_idx(const void* p, long long i) {
    if (g_is64) return ((const long long*)p)[i];
    return (long long)((const int*)p)[i];
}
__device__ __forceinline__ uint32_t smem_u32(const void* p) {
    uint32_t a;
    asm("{ .reg .u64 t; cvta.to.shared.u64 t, %1; cvt.u32.u64 %0, t; }" : "=r"(a) : "l"(p));
    return a;
}
__device__ __forceinline__ uint32_t pack_h2(float a, float b) {
    __half2 h = __floats2half2_rn(a, b);
    return *(uint32_t*)&h;
}
__device__ __forceinline__ void mma16816(float c[4], const uint32_t a[4],
                                         uint32_t b0, uint32_t b1) {
    asm volatile("mma.sync.aligned.m16n8k16.row.col.f32.f16.f16.f32 "
                 "{%0,%1,%2,%3}, {%4,%5,%6,%7}, {%8,%9}, {%0,%1,%2,%3};"
                 : "+f"(c[0]), "+f"(c[1]), "+f"(c[2]), "+f"(c[3])
                 : "r"(a[0]), "r"(a[1]), "r"(a[2]), "r"(a[3]), "r"(b0), "r"(b1));
}
#define LDMX4(r, a)                                                        \
    asm volatile("ldmatrix.sync.aligned.m8n8.x4.shared.b16 {%0,%1,%2,%3}, [%4];" \
        : "=r"((r)[0]), "=r"((r)[1]), "=r"((r)[2]), "=r"((r)[3]) : "r"(a))
#define LDMX2(r, a)                                                        \
    asm volatile("ldmatrix.sync.aligned.m8n8.x2.shared.b16 {%0,%1}, [%2];" \
        : "=r"((r)[0]), "=r"((r)[1]) : "r"(a))

// ---------------- smem layout (bytes) ----------------
#define SM_SRC 0                       // int[384]            1536
#define SM_BE  1536                    // float[64]           256
#define SM_BHI 1792                    // half[192][72]       27648
#define SM_BLO 29440                   // half[192][72]       27648
#define SM_AHI 57088                   // half[384][72]       55296
#define SM_ALO 112384                  // half[384][72]       55296
#define SMEM_BYTES 167680

// ================= kernel 0: dtype detect =================
__global__ void detect_kernel(const int* __restrict__ p) {
    if (threadIdx.x == 0) {
        int any = 0;
        for (int i = 1; i < 256; i += 2) any |= p[i];
        g_is64 = (any == 0) ? 1 : 0;
    }
}

// ================= kernel 1: zero out + denom =================
__global__ void zero_kernel(float4* __restrict__ out, int Nn) {
    int i = blockIdx.x * blockDim.x + threadIdx.x;
    int st = gridDim.x * blockDim.x;
    float4 z = make_float4(0.f, 0.f, 0.f, 0.f);
    int n4 = Nn * 16;
    for (int j = i; j < n4; j += st) out[j] = z;
    float4* dn = (float4*)d_denom;
    for (int j = i; j < Nn; j += st) dn[j] = z;
}

// ================= kernel 2: q = x @ Wq  (+ block 0 builds B image) =================
__global__ void __launch_bounds__(256) prep_kernel(const float* __restrict__ x,
                                                   const float* __restrict__ Wq,
                                                   const float* __restrict__ Wv,
                                                   const float* __restrict__ We,
                                                   const float* __restrict__ Wk,
                                                   int Nn) {
    if (blockIdx.x == 0 && threadIdx.x < 192) {
        int n = threadIdx.x;
        const float* W = (n < 64) ? Wv : ((n < 128) ? We : Wk);
        int nn = n & 63;
        for (int k = 0; k < 64; k++) {
            float w = W[k * 64 + nn];
            __half h = __float2half_rn(w);
            __half l = __float2half_rn(w - __half2float(h));
            d_Bimg[n * 72 + k]            = h;
            d_Bimg[192 * 72 + n * 72 + k] = l;
        }
    }

    __shared__ float sWq[64 * 64];
    int t = threadIdx.x;
    for (int i = t; i < 1024; i += 256) ((float4*)sWq)[i] = ((const float4*)Wq)[i];
    __syncthreads();

    int warp = t >> 5, lane = t & 31;
    int n = blockIdx.x * 8 + warp;
    if (n >= Nn) return;

    float2 x2 = *(const float2*)&x[(size_t)n * 64 + 2 * lane];
    float qa = 0.f, qb = 0.f;
    #pragma unroll
    for (int dd = 0; dd < 32; dd++) {
        float xa = __shfl_sync(0xffffffffu, x2.x, dd);
        float xb = __shfl_sync(0xffffffffu, x2.y, dd);
        float2 w0 = *(const float2*)&sWq[(2 * dd) * 64 + 2 * lane];
        float2 w1 = *(const float2*)&sWq[(2 * dd + 1) * 64 + 2 * lane];
        qa += xa * w0.x + xb * w1.x;
        qb += xa * w0.y + xb * w1.y;
    }
    d_q[(size_t)n * 64 + 2 * lane]     = qa;
    d_q[(size_t)n * 64 + 2 * lane + 1] = qb;
}

// ================= kernel 3: fused edge pass =================
__global__ void __launch_bounds__(NTHR, 1) edge_kernel(const float* __restrict__ x,
                                                       const void*  __restrict__ eidx,
                                                       const float* __restrict__ ea,
                                                       const float* __restrict__ be,
                                                       float* __restrict__ outp,
                                                       float* __restrict__ eo,
                                                       long long Etot) {
    extern __shared__ __align__(16) char smem[];
    uint32_t smb = smem_u32(smem);
    int t = threadIdx.x, w = t >> 5, l = t & 31;
    int g = l >> 2, t4 = l & 3;

    int*   ssrc = (int*)(smem + SM_SRC);
    float* sbe  = (float*)(smem + SM_BE);

    long long ebase = (long long)blockIdx.x * EPB;

    // ---- B copy (55296 B, contiguous hi|lo) ----
    {
        const uint4* bs = (const uint4*)d_Bimg;
        uint4* bd = (uint4*)(smem + SM_BHI);
        #pragma unroll
        for (int i = 0; i < 9; i++) bd[t + NTHR * i] = bs[t + NTHR * i];
    }
    if (t < 64) sbe[t] = be[t];

    // ---- A build: edge = ebase + t, Z = ea * x[nbr], fp16 hi/lo split ----
    {
        long long e = ebase + t;
        bool valid = (e < Etot);
        int src = 0; long long nbr = 0;
        if (valid) { src = (int)load_idx(eidx, e); nbr = load_idx(eidx, Etot + e); }
        ssrc[t] = src;
        const float4* eap = (const float4*)(ea + (size_t)e * 64);
        const float4* xnp = (const float4*)(x + (size_t)nbr * 64);
        char* ah = smem + SM_AHI + t * 144;
        char* al = smem + SM_ALO + t * 144;
        #pragma unroll
        for (int i = 0; i < 8; i++) {
            float z[8];
            if (valid) {
                float4 a0 = eap[2 * i], b0 = xnp[2 * i];
                float4 a1 = eap[2 * i + 1], b1 = xnp[2 * i + 1];
                z[0] = a0.x * b0.x; z[1] = a0.y * b0.y; z[2] = a0.z * b0.z; z[3] = a0.w * b0.w;
                z[4] = a1.x * b1.x; z[5] = a1.y * b1.y; z[6] = a1.z * b1.z; z[7] = a1.w * b1.w;
            } else {
                #pragma unroll
                for (int j = 0; j < 8; j++) z[j] = 0.f;
            }
            uint4 hv, lv;
            float h0, h1;
            h0 = __half2float(__float2half_rn(z[0])); h1 = __half2float(__float2half_rn(z[1]));
            hv.x = pack_h2(z[0], z[1]); lv.x = pack_h2(z[0] - h0, z[1] - h1);
            h0 = __half2float(__float2half_rn(z[2])); h1 = __half2float(__float2half_rn(z[3]));
            hv.y = pack_h2(z[2], z[3]); lv.y = pack_h2(z[2] - h0, z[3] - h1);
            h0 = __half2float(__float2half_rn(z[4])); h1 = __half2float(__float2half_rn(z[5]));
            hv.z = pack_h2(z[4], z[5]); lv.z = pack_h2(z[4] - h0, z[5] - h1);
            h0 = __half2float(__float2half_rn(z[6])); h1 = __half2float(__float2half_rn(z[7]));
            hv.w = pack_h2(z[6], z[7]); lv.w = pack_h2(z[6] - h0, z[7] - h1);
            *(uint4*)(ah + 16 * i) = hv;
            *(uint4*)(al + 16 * i) = lv;
        }
    }
    __syncthreads();

    // ---------------- per-warp: rows rb .. rb+31 (2 m-tiles) ----------------
    int rb = w * 32;

    int  srow[2][2];
    bool vrow[2][2];
    #pragma unroll
    for (int mt = 0; mt < 2; mt++)
        #pragma unroll
        for (int r = 0; r < 2; r++) {
            int row = rb + mt * 16 + g + 8 * r;
            srow[mt][r] = ssrc[row];
            vrow[mt][r] = (ebase + row) < Etot;
        }

    // ---- A fragments via ldmatrix.x4 ----
    uint32_t afh[2][4][4], afl[2][4][4];
    {
        uint32_t rowsel = (uint32_t)(l & 15);
        uint32_t koff = (uint32_t)(l >> 4) * 16;
        #pragma unroll
        for (int mt = 0; mt < 2; mt++) {
            uint32_t ab = smb + SM_AHI + (rb + mt * 16 + rowsel) * 144 + koff;
            #pragma unroll
            for (int ks = 0; ks < 4; ks++) {
                LDMX4(afh[mt][ks], ab + ks * 32);
                LDMX4(afl[mt][ks], ab + (SM_ALO - SM_AHI) + ks * 32);
            }
        }
    }

    // B per-lane base (lanes 0-15 meaningful for x2)
    uint32_t bb = smb + SM_BHI + (uint32_t)(l & 7) * 144 + (uint32_t)((l >> 3) & 1) * 16;

    // q row pointers for this lane's 4 rows
    const float* q00 = d_q + (size_t)srow[0][0] * 64;
    const float* q01 = d_q + (size_t)srow[0][1] * 64;
    const float* q10 = d_q + (size_t)srow[1][0] * 64;
    const float* q11 = d_q + (size_t)srow[1][1] * 64;

    // ---- k path (B cols 128..191), 2-term: (Z_hi + Z_lo) . W_hi ----
    float ps[2][2][4];
    #pragma unroll
    for (int mt = 0; mt < 2; mt++)
        #pragma unroll
        for (int r = 0; r < 2; r++)
            #pragma unroll
            for (int h = 0; h < 4; h++) ps[mt][r][h] = 0.f;

    #pragma unroll
    for (int j = 0; j < 8; j++) {
        float c0[4] = {0.f, 0.f, 0.f, 0.f};
        float c1[4] = {0.f, 0.f, 0.f, 0.f};
        #pragma unroll
        for (int ks = 0; ks < 4; ks++) {
            uint32_t bo = (uint32_t)(128 + 8 * j) * 144 + ks * 32;
            uint32_t bh[2];
            LDMX2(bh, bb + bo);
            mma16816(c0, afh[0][ks], bh[0], bh[1]);
            mma16816(c0, afl[0][ks], bh[0], bh[1]);
            mma16816(c1, afh[1][ks], bh[0], bh[1]);
            mma16816(c1, afl[1][ks], bh[0], bh[1]);
        }
        int jc = 8 * j + 2 * t4;
        float2 qa = *(const float2*)(q00 + jc);
        float2 qb = *(const float2*)(q01 + jc);
        float2 qc = *(const float2*)(q10 + jc);
        float2 qd = *(const float2*)(q11 + jc);
        int h = j >> 1;
        ps[0][0][h] += c0[0] * qa.x + c0[1] * qa.y;
        ps[0][1][h] += c0[2] * qb.x + c0[3] * qb.y;
        ps[1][0][h] += c1[0] * qc.x + c1[1] * qc.y;
        ps[1][1][h] += c1[2] * qd.x + c1[3] * qd.y;
    }

    // quad-reduce + exp -> att
    float att[2][2][4];
    #pragma unroll
    for (int mt = 0; mt < 2; mt++)
        #pragma unroll
        for (int r = 0; r < 2; r++)
            #pragma unroll
            for (int h = 0; h < 4; h++) {
                float v = ps[mt][r][h];
                v += __shfl_xor_sync(0xffffffffu, v, 1);
                v += __shfl_xor_sync(0xffffffffu, v, 2);
                att[mt][r][h] = __expf(v * 0.25f);
            }

    // denom scatter: lane t4 = mt*2+r handles one row
    #pragma unroll
    for (int mt = 0; mt < 2; mt++)
        #pragma unroll
        for (int r = 0; r < 2; r++)
            if (t4 == mt * 2 + r && vrow[mt][r])
                red4(&d_denom[(size_t)srow[mt][r] * 4],
                     make_float4(att[mt][r][0], att[mt][r][1], att[mt][r][2], att[mt][r][3]));

    // ---- v | eo sweep (B cols 0..127), 3-term, B shared across m-tiles ----
    bool even = ((t4 & 1) == 0);
    int colb = even ? (2 * t4) : (2 * (t4 - 1));   // 0 or 4
    int r = even ? 0 : 1;

    #pragma unroll
    for (int j = 0; j < 16; j++) {
        float c[2][4];
        #pragma unroll
        for (int mt = 0; mt < 2; mt++)
            #pragma unroll
            for (int i = 0; i < 4; i++) c[mt][i] = 0.f;

        #pragma unroll
        for (int ks = 0; ks < 4; ks++) {
            uint32_t bo = (uint32_t)(8 * j) * 144 + ks * 32;
            uint32_t bh[2], bl[2];
            LDMX2(bh, bb + bo);
            LDMX2(bl, bb + bo + 27648);
            mma16816(c[0], afh[0][ks], bh[0], bh[1]);
            mma16816(c[0], afh[0][ks], bl[0], bl[1]);
            mma16816(c[0], afl[0][ks], bh[0], bh[1]);
            mma16816(c[1], afh[1][ks], bh[0], bh[1]);
            mma16816(c[1], afh[1][ks], bl[0], bl[1]);
            mma16816(c[1], afl[1][ks], bh[0], bh[1]);
        }

        #pragma unroll
        for (int mt = 0; mt < 2; mt++) {
            float v0 = c[mt][0], v1 = c[mt][1], v2 = c[mt][2], v3 = c[mt][3];
            if (j < 8) {
                int h = j >> 1;
                v0 *= att[mt][0][h]; v1 *= att[mt][0][h];
                v2 *= att[mt][1][h]; v3 *= att[mt][1][h];
            } else {
                int ec = 8 * (j - 8) + 2 * t4;
                float b0 = sbe[ec], b1 = sbe[ec + 1];
                v0 += b0; v1 += b1; v2 += b0; v3 += b1;
            }
            float o0 = __shfl_xor_sync(0xffffffffu, v0, 1);
            float o1 = __shfl_xor_sync(0xffffffffu, v1, 1);
            float o2 = __shfl_xor_sync(0xffffffffu, v2, 1);
            float o3 = __shfl_xor_sync(0xffffffffu, v3, 1);
            float4 vv = even ? make_float4(v0, v1, o0, o1)
                             : make_float4(o2, o3, v2, v3);
            if (vrow[mt][r]) {
                if (j < 8) {
                    red4(outp + (size_t)srow[mt][r] * 64 + 8 * j + colb, vv);
                } else {
                    long long row = ebase + rb + mt * 16 + g + 8 * r;
                    *(float4*)(eo + row * 64 + 8 * (j - 8) + colb) = vv;
                }
            }
        }
    }
}

// ================= kernel 4: normalize =================
__global__ void norm_kernel(float4* __restrict__ out, int Nn) {
    int i = blockIdx.x * blockDim.x + threadIdx.x;
    if (i >= Nn * 16) return;
    int n = i >> 4;
    int h = (i >> 2) & 3;
    float dinv = 1.0f / (d_denom[n * 4 + h] + 1e-16f);
    float4 v = out[i];
    v.x *= dinv; v.y *= dinv; v.z *= dinv; v.w *= dinv;
    out[i] = v;
}

// ================= launch =================
extern "C" void kernel_launch(void* const* d_in, const int* in_sizes, int n_in,
                              void* d_out, int out_size) {
    const float* x   = (const float*)d_in[0];
    const void*  eix = d_in[1];
    const float* ea  = (const float*)d_in[2];
    const float* Wq  = (const float*)d_in[3];
    const float* Wk  = (const float*)d_in[4];
    const float* Wv  = (const float*)d_in[5];
    const float* We  = (const float*)d_in[6];
    const float* be  = (const float*)d_in[7];

    int       Nn   = in_sizes[0] / 64;
    long long Etot = (long long)in_sizes[2] / 64;

    float* outp = (float*)d_out;
    float* eo   = outp + (size_t)Nn * 64;

    static int cfg = 0;
    if (!cfg) {
        cudaFuncSetAttribute(edge_kernel, cudaFuncAttributeMaxDynamicSharedMemorySize, SMEM_BYTES);
        cfg = 1;
    }

    detect_kernel<<<1, 32>>>((const int*)eix);
    zero_kernel<<<2048, 256>>>((float4*)outp, Nn);
    prep_kernel<<<(Nn + 7) / 8, 256>>>(x, Wq, Wv, We, Wk, Nn);
    int eblocks = (int)((Etot + EPB - 1) / EPB);
    edge_kernel<<<eblocks, NTHR, SMEM_BYTES>>>(x, eix, ea, be, outp, eo, Etot);
    norm_kernel<<<(Nn * 16 + 255) / 256, 256>>>((float4*)outp, Nn);
}

// round 7
// speedup vs baseline: 2.4595x; 1.1029x over previous
#include <cuda_runtime.h>
#include <cuda_fp16.h>
#include <cstdint>

#define MAXN 100000
#define EPB  384            // edges per block
#define NTHR 384

// ---------------- device scratch ----------------
__device__ float d_q[(size_t)MAXN * 64];                 // q[n][h*16+c], 25.6 MB
__device__ float d_denom[MAXN * 4];                      // per (node, head)
__device__ __align__(16) __half d_Bimg[2 * 192 * 72];    // [hi|lo][col][k pad 72]
__device__ int g_is64;

// ---------------- helpers ----------------
__device__ __forceinline__ void red4(float* p, float4 v) {
    asm volatile("red.global.add.v4.f32 [%0], {%1, %2, %3, %4};"
                 :: "l"(p), "f"(v.x), "f"(v.y), "f"(v.z), "f"(v.w) : "memory");
}
__device__ __forceinline__ long long load_idx(const void* p, long long i) {
    if (g_is64) return ((const long long*)p)[i];
    return (long long)((const int*)p)[i];
}
__device__ __forceinline__ uint32_t smem_u32(const void* p) {
    uint32_t a;
    asm("{ .reg .u64 t; cvta.to.shared.u64 t, %1; cvt.u32.u64 %0, t; }" : "=r"(a) : "l"(p));
    return a;
}
__device__ __forceinline__ uint32_t pack_h2(float a, float b) {
    __half2 h = __floats2half2_rn(a, b);
    return *(uint32_t*)&h;
}
__device__ __forceinline__ void mma16816(float c[4], const uint32_t a[4],
                                         uint32_t b0, uint32_t b1) {
    asm volatile("mma.sync.aligned.m16n8k16.row.col.f32.f16.f16.f32 "
                 "{%0,%1,%2,%3}, {%4,%5,%6,%7}, {%8,%9}, {%0,%1,%2,%3};"
                 : "+f"(c[0]), "+f"(c[1]), "+f"(c[2]), "+f"(c[3])
                 : "r"(a[0]), "r"(a[1]), "r"(a[2]), "r"(a[3]), "r"(b0), "r"(b1));
}
#define LDMX4(r, a)                                                        \
    asm volatile("ldmatrix.sync.aligned.m8n8.x4.shared.b16 {%0,%1,%2,%3}, [%4];" \
        : "=r"((r)[0]), "=r"((r)[1]), "=r"((r)[2]), "=r"((r)[3]) : "r"(a))
#define LDMX2(r, a)                                                        \
    asm volatile("ldmatrix.sync.aligned.m8n8.x2.shared.b16 {%0,%1}, [%2];" \
        : "=r"((r)[0]), "=r"((r)[1]) : "r"(a))

// ---------------- smem layout (bytes) ----------------
#define SM_SRC 0                       // int[384]            1536
#define SM_BE  1536                    // float[64]           256
#define SM_BHI 1792                    // half[192][72]       27648
#define SM_BLO 29440                   // half[192][72]       27648
#define SM_AHI 57088                   // half[384][72]       55296
#define SM_ALO 112384                  // half[384][72]       55296
#define SMEM_BYTES 167680

// ================= kernel 0: dtype detect =================
__global__ void detect_kernel(const int* __restrict__ p) {
    if (threadIdx.x == 0) {
        int any = 0;
        for (int i = 1; i < 256; i += 2) any |= p[i];
        g_is64 = (any == 0) ? 1 : 0;
    }
}

// ================= kernel 1: zero out + denom =================
__global__ void zero_kernel(float4* __restrict__ out, int Nn) {
    int i = blockIdx.x * blockDim.x + threadIdx.x;
    int st = gridDim.x * blockDim.x;
    float4 z = make_float4(0.f, 0.f, 0.f, 0.f);
    int n4 = Nn * 16;
    for (int j = i; j < n4; j += st) out[j] = z;
    float4* dn = (float4*)d_denom;
    for (int j = i; j < Nn; j += st) dn[j] = z;
}

// ================= kernel 2: q = x @ Wq  (+ block 0 builds B image) =================
__global__ void __launch_bounds__(256) prep_kernel(const float* __restrict__ x,
                                                   const float* __restrict__ Wq,
                                                   const float* __restrict__ Wv,
                                                   const float* __restrict__ We,
                                                   const float* __restrict__ Wk,
                                                   int Nn) {
    if (blockIdx.x == 0 && threadIdx.x < 192) {
        int n = threadIdx.x;
        const float* W = (n < 64) ? Wv : ((n < 128) ? We : Wk);
        int nn = n & 63;
        for (int k = 0; k < 64; k++) {
            float w = W[k * 64 + nn];
            __half h = __float2half_rn(w);
            __half l = __float2half_rn(w - __half2float(h));
            d_Bimg[n * 72 + k]            = h;
            d_Bimg[192 * 72 + n * 72 + k] = l;
        }
    }

    __shared__ float sWq[64 * 64];
    int t = threadIdx.x;
    for (int i = t; i < 1024; i += 256) ((float4*)sWq)[i] = ((const float4*)Wq)[i];
    __syncthreads();

    int warp = t >> 5, lane = t & 31;
    int n = blockIdx.x * 8 + warp;
    if (n >= Nn) return;

    float2 x2 = *(const float2*)&x[(size_t)n * 64 + 2 * lane];
    float qa = 0.f, qb = 0.f;
    #pragma unroll
    for (int dd = 0; dd < 32; dd++) {
        float xa = __shfl_sync(0xffffffffu, x2.x, dd);
        float xb = __shfl_sync(0xffffffffu, x2.y, dd);
        float2 w0 = *(const float2*)&sWq[(2 * dd) * 64 + 2 * lane];
        float2 w1 = *(const float2*)&sWq[(2 * dd + 1) * 64 + 2 * lane];
        qa += xa * w0.x + xb * w1.x;
        qb += xa * w0.y + xb * w1.y;
    }
    d_q[(size_t)n * 64 + 2 * lane]     = qa;
    d_q[(size_t)n * 64 + 2 * lane + 1] = qb;
}

// ================= kernel 3: fused edge pass =================
__global__ void __launch_bounds__(NTHR, 1) edge_kernel(const float* __restrict__ x,
                                                       const void*  __restrict__ eidx,
                                                       const float* __restrict__ ea,
                                                       const float* __restrict__ be,
                                                       float* __restrict__ outp,
                                                       float* __restrict__ eo,
                                                       long long Etot) {
    extern __shared__ __align__(16) char smem[];
    uint32_t smb = smem_u32(smem);
    int t = threadIdx.x, w = t >> 5, l = t & 31;
    int g = l >> 2, t4 = l & 3;

    int*   ssrc = (int*)(smem + SM_SRC);
    float* sbe  = (float*)(smem + SM_BE);

    long long ebase = (long long)blockIdx.x * EPB;

    // ---- B copy (55296 B, contiguous hi|lo) ----
    {
        const uint4* bs = (const uint4*)d_Bimg;
        uint4* bd = (uint4*)(smem + SM_BHI);
        #pragma unroll
        for (int i = 0; i < 9; i++) bd[t + NTHR * i] = bs[t + NTHR * i];
    }
    if (t < 64) sbe[t] = be[t];

    // ---- A build: 8 lanes per edge, coalesced. Z = ea * x[nbr], fp16 hi/lo split ----
    {
        int oct = t & 7;
        int elb = t >> 3;                     // 0..47
        #pragma unroll
        for (int p = 0; p < 8; p++) {
            int eb = elb + 48 * p;            // edge within block
            long long e = ebase + eb;
            bool valid = (e < Etot);
            int src = 0; long long nbr = 0;
            if (valid) { src = (int)load_idx(eidx, e); nbr = load_idx(eidx, Etot + e); }
            if (oct == 0) ssrc[eb] = src;
            #pragma unroll
            for (int h2 = 0; h2 < 2; h2++) {
                float4 a4, x4;
                if (valid) {
                    a4 = *(const float4*)(ea + (size_t)e * 64 + h2 * 32 + oct * 4);
                    x4 = *(const float4*)(x + (size_t)nbr * 64 + h2 * 32 + oct * 4);
                } else {
                    a4 = make_float4(0.f, 0.f, 0.f, 0.f);
                    x4 = a4;
                }
                float z0 = a4.x * x4.x, z1 = a4.y * x4.y;
                float z2 = a4.z * x4.z, z3 = a4.w * x4.w;
                float h0 = __half2float(__float2half_rn(z0));
                float h1 = __half2float(__float2half_rn(z1));
                float h2f = __half2float(__float2half_rn(z2));
                float h3 = __half2float(__float2half_rn(z3));
                uint2 hv = make_uint2(pack_h2(z0, z1), pack_h2(z2, z3));
                uint2 lv = make_uint2(pack_h2(z0 - h0, z1 - h1), pack_h2(z2 - h2f, z3 - h3));
                uint32_t off = (uint32_t)eb * 144 + h2 * 64 + oct * 8;
                *(uint2*)(smem + SM_AHI + off) = hv;
                *(uint2*)(smem + SM_ALO + off) = lv;
            }
        }
    }
    __syncthreads();

    // ---------------- per-warp: rows rb .. rb+31 (2 m-tiles) ----------------
    int rb = w * 32;

    int  srow[2][2];
    bool vrow[2][2];
    #pragma unroll
    for (int mt = 0; mt < 2; mt++)
        #pragma unroll
        for (int r = 0; r < 2; r++) {
            int row = rb + mt * 16 + g + 8 * r;
            srow[mt][r] = ssrc[row];
            vrow[mt][r] = (ebase + row) < Etot;
        }

    // ---- A fragments via ldmatrix.x4 ----
    uint32_t afh[2][4][4], afl[2][4][4];
    {
        uint32_t rowsel = (uint32_t)(l & 15);
        uint32_t koff = (uint32_t)(l >> 4) * 16;
        #pragma unroll
        for (int mt = 0; mt < 2; mt++) {
            uint32_t ab = smb + SM_AHI + (rb + mt * 16 + rowsel) * 144 + koff;
            #pragma unroll
            for (int ks = 0; ks < 4; ks++) {
                LDMX4(afh[mt][ks], ab + ks * 32);
                LDMX4(afl[mt][ks], ab + (SM_ALO - SM_AHI) + ks * 32);
            }
        }
    }

    // B per-lane base (lanes 0-15 meaningful for x2)
    uint32_t bb = smb + SM_BHI + (uint32_t)(l & 7) * 144 + (uint32_t)((l >> 3) & 1) * 16;

    // q row pointers for this lane's 4 rows
    const float* q00 = d_q + (size_t)srow[0][0] * 64;
    const float* q01 = d_q + (size_t)srow[0][1] * 64;
    const float* q10 = d_q + (size_t)srow[1][0] * 64;
    const float* q11 = d_q + (size_t)srow[1][1] * 64;

    // ---- k path (B cols 128..191), 2-term: (Z_hi + Z_lo) . W_hi ----
    float ps[2][2][4];
    #pragma unroll
    for (int mt = 0; mt < 2; mt++)
        #pragma unroll
        for (int r = 0; r < 2; r++)
            #pragma unroll
            for (int h = 0; h < 4; h++) ps[mt][r][h] = 0.f;

    #pragma unroll
    for (int j = 0; j < 8; j++) {
        float c0[4] = {0.f, 0.f, 0.f, 0.f};
        float c1[4] = {0.f, 0.f, 0.f, 0.f};
        #pragma unroll
        for (int ks = 0; ks < 4; ks++) {
            uint32_t bo = (uint32_t)(128 + 8 * j) * 144 + ks * 32;
            uint32_t bh[2];
            LDMX2(bh, bb + bo);
            mma16816(c0, afh[0][ks], bh[0], bh[1]);
            mma16816(c0, afl[0][ks], bh[0], bh[1]);
            mma16816(c1, afh[1][ks], bh[0], bh[1]);
            mma16816(c1, afl[1][ks], bh[0], bh[1]);
        }
        int jc = 8 * j + 2 * t4;
        float2 qa = *(const float2*)(q00 + jc);
        float2 qb = *(const float2*)(q01 + jc);
        float2 qc = *(const float2*)(q10 + jc);
        float2 qd = *(const float2*)(q11 + jc);
        int h = j >> 1;
        ps[0][0][h] += c0[0] * qa.x + c0[1] * qa.y;
        ps[0][1][h] += c0[2] * qb.x + c0[3] * qb.y;
        ps[1][0][h] += c1[0] * qc.x + c1[1] * qc.y;
        ps[1][1][h] += c1[2] * qd.x + c1[3] * qd.y;
    }

    // quad-reduce + exp -> att
    float att[2][2][4];
    #pragma unroll
    for (int mt = 0; mt < 2; mt++)
        #pragma unroll
        for (int r = 0; r < 2; r++)
            #pragma unroll
            for (int h = 0; h < 4; h++) {
                float v = ps[mt][r][h];
                v += __shfl_xor_sync(0xffffffffu, v, 1);
                v += __shfl_xor_sync(0xffffffffu, v, 2);
                att[mt][r][h] = __expf(v * 0.25f);
            }

    // denom scatter: lane t4 = mt*2+r handles one row
    #pragma unroll
    for (int mt = 0; mt < 2; mt++)
        #pragma unroll
        for (int r = 0; r < 2; r++)
            if (t4 == mt * 2 + r && vrow[mt][r])
                red4(&d_denom[(size_t)srow[mt][r] * 4],
                     make_float4(att[mt][r][0], att[mt][r][1], att[mt][r][2], att[mt][r][3]));

    // ---- v | eo sweep (B cols 0..127), 3-term, B shared across m-tiles ----
    bool even = ((t4 & 1) == 0);
    int colb = even ? (2 * t4) : (2 * (t4 - 1));   // 0 or 4
    int r = even ? 0 : 1;

    #pragma unroll
    for (int j = 0; j < 16; j++) {
        float c[2][4];
        #pragma unroll
        for (int mt = 0; mt < 2; mt++)
            #pragma unroll
            for (int i = 0; i < 4; i++) c[mt][i] = 0.f;

        #pragma unroll
        for (int ks = 0; ks < 4; ks++) {
            uint32_t bo = (uint32_t)(8 * j) * 144 + ks * 32;
            uint32_t bh[2], bl[2];
            LDMX2(bh, bb + bo);
            LDMX2(bl, bb + bo + 27648);
            mma16816(c[0], afh[0][ks], bh[0], bh[1]);
            mma16816(c[0], afh[0][ks], bl[0], bl[1]);
            mma16816(c[0], afl[0][ks], bh[0], bh[1]);
            mma16816(c[1], afh[1][ks], bh[0], bh[1]);
            mma16816(c[1], afh[1][ks], bl[0], bl[1]);
            mma16816(c[1], afl[1][ks], bh[0], bh[1]);
        }

        #pragma unroll
        for (int mt = 0; mt < 2; mt++) {
            float v0 = c[mt][0], v1 = c[mt][1], v2 = c[mt][2], v3 = c[mt][3];
            if (j < 8) {
                int h = j >> 1;
                v0 *= att[mt][0][h]; v1 *= att[mt][0][h];
                v2 *= att[mt][1][h]; v3 *= att[mt][1][h];
            } else {
                int ec = 8 * (j - 8) + 2 * t4;
                float b0 = sbe[ec], b1 = sbe[ec + 1];
                v0 += b0; v1 += b1; v2 += b0; v3 += b1;
            }
            float o0 = __shfl_xor_sync(0xffffffffu, v0, 1);
            float o1 = __shfl_xor_sync(0xffffffffu, v1, 1);
            float o2 = __shfl_xor_sync(0xffffffffu, v2, 1);
            float o3 = __shfl_xor_sync(0xffffffffu, v3, 1);
            float4 vv = even ? make_float4(v0, v1, o0, o1)
                             : make_float4(o2, o3, v2, v3);
            if (vrow[mt][r]) {
                if (j < 8) {
                    red4(outp + (size_t)srow[mt][r] * 64 + 8 * j + colb, vv);
                } else {
                    long long row = ebase + rb + mt * 16 + g + 8 * r;
                    *(float4*)(eo + row * 64 + 8 * (j - 8) + colb) = vv;
                }
            }
        }
    }
}

// ================= kernel 4: normalize =================
__global__ void norm_kernel(float4* __restrict__ out, int Nn) {
    int i = blockIdx.x * blockDim.x + threadIdx.x;
    if (i >= Nn * 16) return;
    int n = i >> 4;
    int h = (i >> 2) & 3;
    float dinv = 1.0f / (d_denom[n * 4 + h] + 1e-16f);
    float4 v = out[i];
    v.x *= dinv; v.y *= dinv; v.z *= dinv; v.w *= dinv;
    out[i] = v;
}

// ================= launch =================
extern "C" void kernel_launch(void* const* d_in, const int* in_sizes, int n_in,
                              void* d_out, int out_size) {
    const float* x   = (const float*)d_in[0];
    const void*  eix = d_in[1];
    const float* ea  = (const float*)d_in[2];
    const float* Wq  = (const float*)d_in[3];
    const float* Wk  = (const float*)d_in[4];
    const float* Wv  = (const float*)d_in[5];
    const float* We  = (const float*)d_in[6];
    const float* be  = (const float*)d_in[7];

    int       Nn   = in_sizes[0] / 64;
    long long Etot = (long long)in_sizes[2] / 64;

    float* outp = (float*)d_out;
    float* eo   = outp + (size_t)Nn * 64;

    static int cfg = 0;
    if (!cfg) {
        cudaFuncSetAttribute(edge_kernel, cudaFuncAttributeMaxDynamicSharedMemorySize, SMEM_BYTES);
        cfg = 1;
    }

    detect_kernel<<<1, 32>>>((const int*)eix);
    zero_kernel<<<2048, 256>>>((float4*)outp, Nn);
    prep_kernel<<<(Nn + 7) / 8, 256>>>(x, Wq, Wv, We, Wk, Nn);
    int eblocks = (int)((Etot + EPB - 1) / EPB);
    edge_kernel<<<eblocks, NTHR, SMEM_BYTES>>>(x, eix, ea, be, outp, eo, Etot);
    norm_kernel<<<(Nn * 16 + 255) / 256, 256>>>((float4*)outp, Nn);
}